// round 1
// baseline (speedup 1.0000x reference)
#include <cuda_runtime.h>
#include <cuda_bf16.h>
#include <cstdint>
#include <cstddef>

#define H    1024
#define FF   2048
#define G3   3072
#define SEQ  64      // batch dim of x, acts as GRU sequence length
#define T    30
#define NSEG 8
#define SUB  4
#define R    240     // T * NSEG independent GRU runs
#define DT   (1.0f/32.0f)

// ---------------- scratch (static device globals; no allocation) ----------
__device__ float g_h[H];
__device__ float g_heff[H];
__device__ float g_ksum[H];
__device__ float g_t1[FF];
__device__ float g_t2[FF];
__device__ float g_traj[NSEG][H];
__device__ float g_gi0[(size_t)T * SEQ * G3];   // precomputed x@wi0^T + bi0
__device__ float g_h1[2][R * H];                // ping-pong layer-1 hidden
__device__ float g_h2[2][R * H];                // ping-pong layer-2 hidden

__device__ __forceinline__ float sigf(float v) { return 1.f / (1.f + expf(-v)); }

// ---------------- ODE: zero init ------------------------------------------
__global__ void zero_h() { g_h[threadIdx.x] = 0.f; }   // <<<1,1024>>>

// ---------------- ODE: fused GEMV stages -----------------------------------
// stage 1: t1 = tanh(W1 @ v + b1), v = (mode==0 ? h : heff)
// stage 2: t2 = tanh(W2 @ t1 + b2)
// stage 3: k  = W3 @ t2 + b3, RK4 combine fused in epilogue
__global__ void ode_gemv(const float* __restrict__ W, const float* __restrict__ bias,
                         int K, int stage, int mode, int traj_idx) {
    __shared__ __align__(16) float sv[FF];
    const float* v = (stage == 1) ? (mode == 0 ? g_h : g_heff)
                                  : (stage == 2 ? g_t1 : g_t2);
    for (int i = threadIdx.x; i < K; i += blockDim.x) sv[i] = v[i];
    __syncthreads();

    int warp = threadIdx.x >> 5, lane = threadIdx.x & 31;
    int row  = (blockIdx.x << 3) + warp;   // 8 rows per block
    const float* wr = W + (size_t)row * K;
    float s = 0.f;
    for (int k = lane * 4; k < K; k += 128) {
        float4 wv = *(const float4*)(wr + k);
        float4 vv = *(const float4*)(sv + k);
        s += wv.x * vv.x + wv.y * vv.y + wv.z * vv.z + wv.w * vv.w;
    }
#pragma unroll
    for (int o = 16; o; o >>= 1) s += __shfl_xor_sync(0xffffffffu, s, o);

    if (lane == 0) {
        s += bias[row];
        if (stage == 1)      g_t1[row] = tanhf(s);
        else if (stage == 2) g_t2[row] = tanhf(s);
        else {
            float kv = s;
            if (mode == 0)      { g_ksum[row] = kv;           g_heff[row] = g_h[row] + 0.5f * DT * kv; }
            else if (mode == 1) { g_ksum[row] += 2.f * kv;    g_heff[row] = g_h[row] + 0.5f * DT * kv; }
            else if (mode == 2) { g_ksum[row] += 2.f * kv;    g_heff[row] = g_h[row] + DT * kv; }
            else {
                float hn = g_h[row] + (DT / 6.f) * (g_ksum[row] + kv);
                g_h[row] = hn;
                if (traj_idx >= 0) g_traj[traj_idx][row] = hn;
            }
        }
    }
}

// ---------------- gi0 precompute: (T*SEQ) x G3 = x @ wi0^T + bi0 -----------
// grid (T, G3/64), block 256 (16x16), thread tile 4x4, K-chunk 16
__global__ void gi0_gemm(const float* __restrict__ x, const float* __restrict__ wi0,
                         const float* __restrict__ bi0) {
    __shared__ __align__(16) float As[16][68];
    __shared__ __align__(16) float Ws[16][68];
    int t = blockIdx.x, n0 = blockIdx.y * 64;
    int tid = threadIdx.x, tx = tid & 15, ty = tid >> 4;
    float acc[4][4] = {};

    for (int k0 = 0; k0 < H; k0 += 16) {
#pragma unroll
        for (int j = 0; j < 4; j++) {
            int e = tid + j * 256;
            int kc = e & 15, row = e >> 4;
            As[kc][row] = x[((size_t)row * T + t) * H + k0 + kc];           // x[b][t][k]
            Ws[kc][row] = wi0[(size_t)(n0 + row) * H + k0 + kc];
        }
        __syncthreads();
#pragma unroll
        for (int kk = 0; kk < 16; kk++) {
            float4 a = *(const float4*)(&As[kk][ty * 4]);
            float4 w = *(const float4*)(&Ws[kk][tx * 4]);
            float av[4] = {a.x, a.y, a.z, a.w};
            float wv[4] = {w.x, w.y, w.z, w.w};
#pragma unroll
            for (int i = 0; i < 4; i++)
#pragma unroll
                for (int j = 0; j < 4; j++) acc[i][j] += av[i] * wv[j];
        }
        __syncthreads();
    }
#pragma unroll
    for (int i = 0; i < 4; i++) {
        int b = ty * 4 + i;
        size_t base = ((size_t)t * SEQ + b) * G3 + n0;
#pragma unroll
        for (int j = 0; j < 4; j++) {
            int c = tx * 4 + j;
            g_gi0[base + c] = acc[i][j] + bi0[n0 + c];
        }
    }
}

// ---------------- init h1/h2 from trajectory -------------------------------
__global__ void init_states() {      // <<<R, H>>>
    int r = blockIdx.x, j = threadIdx.x;
    float v = g_traj[r & 7][j];      // run r = t*8 + i  ->  init = traj[i]
    g_h1[0][(size_t)r * H + j] = v;
    g_h2[0][(size_t)r * H + j] = v;
}

// ---------------- GRU layer 0 step: gh0 GEMM + fused cell update -----------
// grid (4, 32): BM=64 runs x BN=32 hidden cols (x3 gates). block 256 (16x16)
__global__ void gru_l0(const float* __restrict__ wh0, const float* __restrict__ bh0,
                       int step, int src) {
    __shared__ float As[32][65];
    __shared__ float Ws[32][97];
    int r0 = blockIdx.x * 64, n0 = blockIdx.y * 32;
    int tid = threadIdx.x, tx = tid & 15, ty = tid >> 4;
    const float* h1s = g_h1[src];
    float acc[3][4][2] = {};

    for (int k0 = 0; k0 < H; k0 += 32) {
#pragma unroll
        for (int j = 0; j < 8; j++) {              // A tile: 64 x 32
            int e = tid + j * 256;
            int kc = e & 31, row = e >> 5;
            int r = r0 + row;
            As[kc][row] = (r < R) ? h1s[(size_t)r * H + k0 + kc] : 0.f;
        }
#pragma unroll
        for (int j = 0; j < 12; j++) {             // W tile: 96 x 32 (3 gates)
            int e = tid + j * 256;
            int kc = e & 31, wr = e >> 5;
            int gate = wr >> 5, c = wr & 31;
            Ws[kc][wr] = wh0[(size_t)(gate * H + n0 + c) * H + k0 + kc];
        }
        __syncthreads();
#pragma unroll
        for (int kk = 0; kk < 32; kk++) {
            float a[4], w[3][2];
#pragma unroll
            for (int u = 0; u < 4; u++) a[u] = As[kk][ty + 16 * u];
#pragma unroll
            for (int g = 0; g < 3; g++) {
                w[g][0] = Ws[kk][g * 32 + tx];
                w[g][1] = Ws[kk][g * 32 + tx + 16];
            }
#pragma unroll
            for (int g = 0; g < 3; g++)
#pragma unroll
                for (int u = 0; u < 4; u++)
#pragma unroll
                    for (int v = 0; v < 2; v++) acc[g][u][v] += a[u] * w[g][v];
        }
        __syncthreads();
    }

    float* h1d = g_h1[src ^ 1];
#pragma unroll
    for (int u = 0; u < 4; u++) {
        int r = r0 + ty + 16 * u;
        if (r >= R) continue;
        int t = r >> 3;
        const float* gi = g_gi0 + ((size_t)(t * SEQ + step)) * G3;
#pragma unroll
        for (int v = 0; v < 2; v++) {
            int j = n0 + tx + 16 * v;
            float ghr = acc[0][u][v] + bh0[j];
            float ghz = acc[1][u][v] + bh0[H + j];
            float ghn = acc[2][u][v] + bh0[2 * H + j];
            float rg = sigf(gi[j] + ghr);
            float z  = sigf(gi[H + j] + ghz);
            float n  = tanhf(gi[2 * H + j] + rg * ghn);
            float hp = h1s[(size_t)r * H + j];
            h1d[(size_t)r * H + j] = (1.f - z) * n + z * hp;
        }
    }
}

// ---------------- GRU layer 1 step: gi1 + gh1 GEMMs + fused update + out ---
__global__ void gru_l1(const float* __restrict__ wi1, const float* __restrict__ bi1,
                       const float* __restrict__ wh1, const float* __restrict__ bh1,
                       float* __restrict__ out, int step, int src) {
    __shared__ float A1[32][65];
    __shared__ float A2[32][65];
    __shared__ float W1[32][97];
    __shared__ float W2[32][97];
    int r0 = blockIdx.x * 64, n0 = blockIdx.y * 32;
    int tid = threadIdx.x, tx = tid & 15, ty = tid >> 4;
    const float* h1n = g_h1[src ^ 1];   // new h1 from gru_l0 this step
    const float* h2s = g_h2[src];
    float accI[3][4][2] = {};
    float accH[3][4][2] = {};

    for (int k0 = 0; k0 < H; k0 += 32) {
#pragma unroll
        for (int j = 0; j < 8; j++) {
            int e = tid + j * 256;
            int kc = e & 31, row = e >> 5;
            int r = r0 + row;
            A1[kc][row] = (r < R) ? h1n[(size_t)r * H + k0 + kc] : 0.f;
            A2[kc][row] = (r < R) ? h2s[(size_t)r * H + k0 + kc] : 0.f;
        }
#pragma unroll
        for (int j = 0; j < 12; j++) {
            int e = tid + j * 256;
            int kc = e & 31, wr = e >> 5;
            int gate = wr >> 5, c = wr & 31;
            W1[kc][wr] = wi1[(size_t)(gate * H + n0 + c) * H + k0 + kc];
            W2[kc][wr] = wh1[(size_t)(gate * H + n0 + c) * H + k0 + kc];
        }
        __syncthreads();
#pragma unroll
        for (int kk = 0; kk < 32; kk++) {
            float a1[4], a2[4], w1[3][2], w2[3][2];
#pragma unroll
            for (int u = 0; u < 4; u++) {
                a1[u] = A1[kk][ty + 16 * u];
                a2[u] = A2[kk][ty + 16 * u];
            }
#pragma unroll
            for (int g = 0; g < 3; g++) {
                w1[g][0] = W1[kk][g * 32 + tx];  w1[g][1] = W1[kk][g * 32 + tx + 16];
                w2[g][0] = W2[kk][g * 32 + tx];  w2[g][1] = W2[kk][g * 32 + tx + 16];
            }
#pragma unroll
            for (int g = 0; g < 3; g++)
#pragma unroll
                for (int u = 0; u < 4; u++)
#pragma unroll
                    for (int v = 0; v < 2; v++) {
                        accI[g][u][v] += a1[u] * w1[g][v];
                        accH[g][u][v] += a2[u] * w2[g][v];
                    }
        }
        __syncthreads();
    }

    float* h2d = g_h2[src ^ 1];
#pragma unroll
    for (int u = 0; u < 4; u++) {
        int r = r0 + ty + 16 * u;
        if (r >= R) continue;
#pragma unroll
        for (int v = 0; v < 2; v++) {
            int j = n0 + tx + 16 * v;
            float gir = accI[0][u][v] + bi1[j];
            float giz = accI[1][u][v] + bi1[H + j];
            float gin = accI[2][u][v] + bi1[2 * H + j];
            float ghr = accH[0][u][v] + bh1[j];
            float ghz = accH[1][u][v] + bh1[H + j];
            float ghn = accH[2][u][v] + bh1[2 * H + j];
            float rg = sigf(gir + ghr);
            float z  = sigf(giz + ghz);
            float n  = tanhf(gin + rg * ghn);
            float hp = h2s[(size_t)r * H + j];
            float hn = (1.f - z) * n + z * hp;
            h2d[(size_t)r * H + j] = hn;
            out[((size_t)step * R + r) * H + j] = hn;   // out[b=step][r][j]
        }
    }
}

// ---------------- launcher --------------------------------------------------
extern "C" void kernel_launch(void* const* d_in, const int* in_sizes, int n_in,
                              void* d_out, int out_size) {
    const float* x   = (const float*)d_in[0];
    const float* w1  = (const float*)d_in[1];
    const float* b1  = (const float*)d_in[2];
    const float* w2  = (const float*)d_in[3];
    const float* b2  = (const float*)d_in[4];
    const float* w3  = (const float*)d_in[5];
    const float* b3  = (const float*)d_in[6];
    const float* wi0 = (const float*)d_in[7];
    const float* wh0 = (const float*)d_in[8];
    const float* bi0 = (const float*)d_in[9];
    const float* bh0 = (const float*)d_in[10];
    const float* wi1 = (const float*)d_in[11];
    const float* wh1 = (const float*)d_in[12];
    const float* bi1 = (const float*)d_in[13];
    const float* bh1 = (const float*)d_in[14];
    float* out = (float*)d_out;

    zero_h<<<1, 1024>>>();

    // gi0 precompute (independent of ODE, ordered on same stream)
    gi0_gemm<<<dim3(T, G3 / 64), 256>>>(x, wi0, bi0);

    // ODE trajectory: 8 intervals x 4 RK4 substeps x 4 evals x 3 GEMVs
    for (int iv = 0; iv < NSEG; iv++)
        for (int sb = 0; sb < SUB; sb++)
            for (int m = 0; m < 4; m++) {
                ode_gemv<<<FF / 8, 256>>>(w1, b1, H,  1, m, -1);
                ode_gemv<<<FF / 8, 256>>>(w2, b2, FF, 2, m, -1);
                int ti = (m == 3 && sb == SUB - 1) ? iv : -1;
                ode_gemv<<<H / 8, 256>>>(w3, b3, FF, 3, m, ti);
            }

    init_states<<<R, H>>>();

    // 64 sequential GRU steps over 240 parallel runs
    for (int step = 0; step < SEQ; step++) {
        int src = step & 1;
        gru_l0<<<dim3(4, 32), 256>>>(wh0, bh0, step, src);
        gru_l1<<<dim3(4, 32), 256>>>(wi1, bi1, wh1, bh1, out, step, src);
    }
}